// round 1
// baseline (speedup 1.0000x reference)
#include <cuda_runtime.h>

// Problem constants
#define BB 4
#define SS 2048
#define DD 1024
#define HH 16
#define DKK 64
#define MTOT (BB * SS)   // 8192

// Scratch (allocation-free: __device__ globals)
__device__ float g_Q[BB * HH * SS * DKK];     // [B,H,S,DK]
__device__ float g_K[BB * HH * SS * DKK];
__device__ float g_V[BB * HH * SS * DKK];
__device__ float g_ctx[BB * SS * DD];         // merged heads [B,S,D]

// ---------------------------------------------------------------------------
// GEMM body: C[M=8192, N=1024] = A[8192,1024] @ W[1024,1024] + bias
// 128x128 tile, BK=16, 256 threads, 8x8 per-thread register tile.
// MODE 0: C row-major [M, D]
// MODE 1: C head-major [B, H, S, DK]  (m = b*S+s, n = h*DK+d)
// ---------------------------------------------------------------------------
template <int MODE>
__device__ __forceinline__ void gemm_body(const float* __restrict__ A,
                                          const float* __restrict__ W,
                                          const float* __restrict__ bias,
                                          float* __restrict__ C) {
    __shared__ float As[16][128];   // A^T tile: As[k][m]
    __shared__ float Ws[16][128];   // Ws[k][n]

    const int tid = threadIdx.x;
    const int tr = tid >> 4;        // 0..15
    const int tc = tid & 15;        // 0..15
    const int m0 = blockIdx.y * 128;
    const int n0 = blockIdx.x * 128;

    float acc[8][8];
#pragma unroll
    for (int i = 0; i < 8; i++)
#pragma unroll
        for (int j = 0; j < 8; j++) acc[i][j] = 0.0f;

    for (int k0 = 0; k0 < DD; k0 += 16) {
        // Load A tile (128x16) transposed into As
#pragma unroll
        for (int it = 0; it < 2; it++) {
            int idx = tid + it * 256;          // 0..511 float4s
            int row = idx >> 2;                // 0..127
            int c4  = (idx & 3) << 2;          // 0,4,8,12
            float4 v = *(const float4*)(A + (size_t)(m0 + row) * DD + k0 + c4);
            As[c4 + 0][row] = v.x;
            As[c4 + 1][row] = v.y;
            As[c4 + 2][row] = v.z;
            As[c4 + 3][row] = v.w;
        }
        // Load W tile (16x128)
#pragma unroll
        for (int it = 0; it < 2; it++) {
            int idx = tid + it * 256;          // 0..511 float4s
            int row = idx >> 5;                // 0..15
            int c4  = (idx & 31) << 2;         // 0..124
            *(float4*)(&Ws[row][c4]) =
                *(const float4*)(W + (size_t)(k0 + row) * DD + n0 + c4);
        }
        __syncthreads();

#pragma unroll
        for (int kk = 0; kk < 16; kk++) {
            float a[8], b[8];
            *(float4*)(a)     = *(const float4*)(&As[kk][tr * 8]);
            *(float4*)(a + 4) = *(const float4*)(&As[kk][tr * 8 + 4]);
            *(float4*)(b)     = *(const float4*)(&Ws[kk][tc * 8]);
            *(float4*)(b + 4) = *(const float4*)(&Ws[kk][tc * 8 + 4]);
#pragma unroll
            for (int i = 0; i < 8; i++)
#pragma unroll
                for (int j = 0; j < 8; j++) acc[i][j] += a[i] * b[j];
        }
        __syncthreads();
    }

    // Epilogue
#pragma unroll
    for (int i = 0; i < 8; i++) {
        int m = m0 + tr * 8 + i;
#pragma unroll
        for (int j = 0; j < 8; j++) {
            int n = n0 + tc * 8 + j;
            float v = acc[i][j] + bias[n];
            if (MODE == 1) {
                int b_ = m >> 11;          // / S
                int s_ = m & (SS - 1);
                int h_ = n >> 6;           // / DK
                int d_ = n & (DKK - 1);
                C[(((size_t)(b_ * HH + h_)) * SS + s_) * DKK + d_] = v;
            } else {
                C[(size_t)m * DD + n] = v;
            }
        }
    }
}

__global__ void __launch_bounds__(256) qkv_proj_kernel(
    const float* __restrict__ xq, const float* __restrict__ xk,
    const float* __restrict__ xv,
    const float* __restrict__ Wq, const float* __restrict__ bq,
    const float* __restrict__ Wk, const float* __restrict__ bk,
    const float* __restrict__ Wv, const float* __restrict__ bv) {
    const float* A;
    const float* W;
    const float* bias;
    float* C;
    if (blockIdx.z == 0)      { A = xq; W = Wq; bias = bq; C = g_Q; }
    else if (blockIdx.z == 1) { A = xk; W = Wk; bias = bk; C = g_K; }
    else                      { A = xv; W = Wv; bias = bv; C = g_V; }
    gemm_body<1>(A, W, bias, C);
}

__global__ void __launch_bounds__(256) out_proj_kernel(
    const float* __restrict__ Wo, const float* __restrict__ bo,
    float* __restrict__ out) {
    gemm_body<0>(g_ctx, Wo, bo, out);
}

// ---------------------------------------------------------------------------
// Flash attention: one block per (q-tile of 64, batch-head).
// 256 threads, 4x4 register tile over a 64x64 score tile.
// Shared: qs[d][r] (scaled Q^T), ks[d][c] (K^T), vs[k][d]. P^T reuses ks.
// ---------------------------------------------------------------------------
__global__ void __launch_bounds__(256) attn_kernel() {
    __shared__ float qs[64 * 64];   // qs[d*64 + r]
    __shared__ float ks[64 * 64];   // ks[d*64 + c]; later pT[c*64 + r]
    __shared__ float vs[64 * 64];   // vs[k*64 + d]

    const int tid = threadIdx.x;
    const int tr = tid >> 4;    // 0..15 -> rows tr*4..tr*4+3
    const int tc = tid & 15;    // 0..15 -> cols tc*4..tc*4+3
    const int qt = blockIdx.x;  // q tile
    const int bh = blockIdx.y;  // b*H + h

    const float* Qb = g_Q + ((size_t)bh * SS + qt * 64) * DKK;
    const float* Kb = g_K + (size_t)bh * SS * DKK;
    const float* Vb = g_V + (size_t)bh * SS * DKK;

    const float scale = 0.125f;  // 1/sqrt(64)

    // Load Q tile transposed + pre-scaled
    for (int i = tid; i < 1024; i += 256) {
        int r  = i >> 4;
        int c4 = (i & 15) << 2;
        float4 v = *(const float4*)(Qb + r * 64 + c4);
        qs[(c4 + 0) * 64 + r] = v.x * scale;
        qs[(c4 + 1) * 64 + r] = v.y * scale;
        qs[(c4 + 2) * 64 + r] = v.z * scale;
        qs[(c4 + 3) * 64 + r] = v.w * scale;
    }

    float m_i[4], l_i[4], o[4][4];
#pragma unroll
    for (int i = 0; i < 4; i++) {
        m_i[i] = -1e30f;
        l_i[i] = 0.0f;
#pragma unroll
        for (int j = 0; j < 4; j++) o[i][j] = 0.0f;
    }
    __syncthreads();

    for (int kt = 0; kt < SS / 64; kt++) {
        // Load K (transposed) and V tiles
        for (int i = tid; i < 1024; i += 256) {
            int r  = i >> 4;
            int c4 = (i & 15) << 2;
            const float* kp = Kb + ((size_t)(kt * 64 + r)) * 64 + c4;
            float4 kv = *(const float4*)kp;
            ks[(c4 + 0) * 64 + r] = kv.x;
            ks[(c4 + 1) * 64 + r] = kv.y;
            ks[(c4 + 2) * 64 + r] = kv.z;
            ks[(c4 + 3) * 64 + r] = kv.w;
            const float* vp = Vb + ((size_t)(kt * 64 + r)) * 64 + c4;
            *(float4*)(vs + r * 64 + c4) = *(const float4*)vp;
        }
        __syncthreads();

        // S = (Q*scale) K^T  (64x64, each thread 4x4)
        float sacc[4][4];
#pragma unroll
        for (int i = 0; i < 4; i++)
#pragma unroll
            for (int j = 0; j < 4; j++) sacc[i][j] = 0.0f;

#pragma unroll 8
        for (int kk = 0; kk < 64; kk++) {
            float4 q = *(const float4*)(qs + kk * 64 + tr * 4);
            float4 k = *(const float4*)(ks + kk * 64 + tc * 4);
            float qa[4] = {q.x, q.y, q.z, q.w};
            float ka[4] = {k.x, k.y, k.z, k.w};
#pragma unroll
            for (int i = 0; i < 4; i++)
#pragma unroll
                for (int j = 0; j < 4; j++) sacc[i][j] += qa[i] * ka[j];
        }
        __syncthreads();   // everyone done reading ks before it becomes pT

        // Online softmax + write P^T into ks buffer
        float* pT = ks;
#pragma unroll
        for (int i = 0; i < 4; i++) {
            float mt = fmaxf(fmaxf(sacc[i][0], sacc[i][1]),
                             fmaxf(sacc[i][2], sacc[i][3]));
#pragma unroll
            for (int off = 8; off >= 1; off >>= 1)
                mt = fmaxf(mt, __shfl_xor_sync(0xffffffffu, mt, off));
            float mn = fmaxf(m_i[i], mt);
            float corr = __expf(m_i[i] - mn);
            m_i[i] = mn;
            float p[4], rs = 0.0f;
#pragma unroll
            for (int j = 0; j < 4; j++) {
                p[j] = __expf(sacc[i][j] - mn);
                rs += p[j];
            }
#pragma unroll
            for (int off = 8; off >= 1; off >>= 1)
                rs += __shfl_xor_sync(0xffffffffu, rs, off);
            l_i[i] = l_i[i] * corr + rs;
#pragma unroll
            for (int j = 0; j < 4; j++) {
                o[i][j] *= corr;
                pT[(tc * 4 + j) * 64 + tr * 4 + i] = p[j];
            }
        }
        __syncthreads();

        // O += P V   (each thread 4 rows x 4 d-cols)
#pragma unroll 8
        for (int kk = 0; kk < 64; kk++) {
            float4 p = *(const float4*)(pT + kk * 64 + tr * 4);
            float4 v = *(const float4*)(vs + kk * 64 + tc * 4);
            float pa[4] = {p.x, p.y, p.z, p.w};
            float va[4] = {v.x, v.y, v.z, v.w};
#pragma unroll
            for (int i = 0; i < 4; i++)
#pragma unroll
                for (int j = 0; j < 4; j++) o[i][j] += pa[i] * va[j];
        }
        __syncthreads();   // before next tile overwrites ks/vs
    }

    // Epilogue: ctx[b][s][h*64+d] = O / l
    const int b_ = bh >> 4;
    const int h_ = bh & 15;
#pragma unroll
    for (int i = 0; i < 4; i++) {
        int s_ = qt * 64 + tr * 4 + i;
        float inv = 1.0f / l_i[i];
#pragma unroll
        for (int j = 0; j < 4; j++) {
            int d_ = tc * 4 + j;
            g_ctx[((size_t)(b_ * SS + s_)) * DD + h_ * DKK + d_] = o[i][j] * inv;
        }
    }
}

extern "C" void kernel_launch(void* const* d_in, const int* in_sizes, int n_in,
                              void* d_out, int out_size) {
    const float* query = (const float*)d_in[0];
    const float* key_i = (const float*)d_in[1];
    const float* value = (const float*)d_in[2];
    const float* Wq = (const float*)d_in[3];
    const float* bq = (const float*)d_in[4];
    const float* Wk = (const float*)d_in[5];
    const float* bk = (const float*)d_in[6];
    const float* Wv = (const float*)d_in[7];
    const float* bv = (const float*)d_in[8];
    const float* Wo = (const float*)d_in[9];
    const float* bo = (const float*)d_in[10];
    float* out = (float*)d_out;

    dim3 gProj(DD / 128, MTOT / 128, 3);   // (8, 64, 3)
    qkv_proj_kernel<<<gProj, 256>>>(query, key_i, value, Wq, bq, Wk, bk, Wv, bv);

    dim3 gAttn(SS / 64, BB * HH);          // (32, 64)
    attn_kernel<<<gAttn, 256>>>();

    dim3 gOut(DD / 128, MTOT / 128);       // (8, 64)
    out_proj_kernel<<<gOut, 256>>>(Wo, bo, out);
}

// round 2
// speedup vs baseline: 1.0000x; 1.0000x over previous
#include <cuda_runtime.h>

// Problem constants
#define BB 4
#define SS 2048
#define DD 1024
#define HH 16
#define DKK 64
#define MTOT (BB * SS)   // 8192

// Scratch (allocation-free: __device__ globals)
__device__ float g_Q[BB * HH * SS * DKK];     // [B,H,S,DK]
__device__ float g_K[BB * HH * SS * DKK];
__device__ float g_V[BB * HH * SS * DKK];
__device__ float g_ctx[BB * SS * DD];         // merged heads [B,S,D]

// ---------------------------------------------------------------------------
// GEMM body: C[M=8192, N=1024] = A[8192,1024] @ W[1024,1024] + bias
// 128x128 tile, BK=16, 256 threads, 8x8 per-thread register tile.
// MODE 0: C row-major [M, D]
// MODE 1: C head-major [B, H, S, DK]  (m = b*S+s, n = h*DK+d)
// ---------------------------------------------------------------------------
template <int MODE>
__device__ __forceinline__ void gemm_body(const float* __restrict__ A,
                                          const float* __restrict__ W,
                                          const float* __restrict__ bias,
                                          float* __restrict__ C) {
    __shared__ float As[16][128];   // A^T tile: As[k][m]
    __shared__ float Ws[16][128];   // Ws[k][n]

    const int tid = threadIdx.x;
    const int tr = tid >> 4;        // 0..15
    const int tc = tid & 15;        // 0..15
    const int m0 = blockIdx.y * 128;
    const int n0 = blockIdx.x * 128;

    float acc[8][8];
#pragma unroll
    for (int i = 0; i < 8; i++)
#pragma unroll
        for (int j = 0; j < 8; j++) acc[i][j] = 0.0f;

    for (int k0 = 0; k0 < DD; k0 += 16) {
        // Load A tile (128x16) transposed into As
#pragma unroll
        for (int it = 0; it < 2; it++) {
            int idx = tid + it * 256;          // 0..511 float4s
            int row = idx >> 2;                // 0..127
            int c4  = (idx & 3) << 2;          // 0,4,8,12
            float4 v = *(const float4*)(A + (size_t)(m0 + row) * DD + k0 + c4);
            As[c4 + 0][row] = v.x;
            As[c4 + 1][row] = v.y;
            As[c4 + 2][row] = v.z;
            As[c4 + 3][row] = v.w;
        }
        // Load W tile (16x128)
#pragma unroll
        for (int it = 0; it < 2; it++) {
            int idx = tid + it * 256;          // 0..511 float4s
            int row = idx >> 5;                // 0..15
            int c4  = (idx & 31) << 2;         // 0..124
            *(float4*)(&Ws[row][c4]) =
                *(const float4*)(W + (size_t)(k0 + row) * DD + n0 + c4);
        }
        __syncthreads();

#pragma unroll
        for (int kk = 0; kk < 16; kk++) {
            float a[8], b[8];
            *(float4*)(a)     = *(const float4*)(&As[kk][tr * 8]);
            *(float4*)(a + 4) = *(const float4*)(&As[kk][tr * 8 + 4]);
            *(float4*)(b)     = *(const float4*)(&Ws[kk][tc * 8]);
            *(float4*)(b + 4) = *(const float4*)(&Ws[kk][tc * 8 + 4]);
#pragma unroll
            for (int i = 0; i < 8; i++)
#pragma unroll
                for (int j = 0; j < 8; j++) acc[i][j] += a[i] * b[j];
        }
        __syncthreads();
    }

    // Epilogue
#pragma unroll
    for (int i = 0; i < 8; i++) {
        int m = m0 + tr * 8 + i;
#pragma unroll
        for (int j = 0; j < 8; j++) {
            int n = n0 + tc * 8 + j;
            float v = acc[i][j] + bias[n];
            if (MODE == 1) {
                int b_ = m >> 11;          // / S
                int s_ = m & (SS - 1);
                int h_ = n >> 6;           // / DK
                int d_ = n & (DKK - 1);
                C[(((size_t)(b_ * HH + h_)) * SS + s_) * DKK + d_] = v;
            } else {
                C[(size_t)m * DD + n] = v;
            }
        }
    }
}

__global__ void __launch_bounds__(256) qkv_proj_kernel(
    const float* __restrict__ xq, const float* __restrict__ xk,
    const float* __restrict__ xv,
    const float* __restrict__ Wq, const float* __restrict__ bq,
    const float* __restrict__ Wk, const float* __restrict__ bk,
    const float* __restrict__ Wv, const float* __restrict__ bv) {
    const float* A;
    const float* W;
    const float* bias;
    float* C;
    if (blockIdx.z == 0)      { A = xq; W = Wq; bias = bq; C = g_Q; }
    else if (blockIdx.z == 1) { A = xk; W = Wk; bias = bk; C = g_K; }
    else                      { A = xv; W = Wv; bias = bv; C = g_V; }
    gemm_body<1>(A, W, bias, C);
}

__global__ void __launch_bounds__(256) out_proj_kernel(
    const float* __restrict__ Wo, const float* __restrict__ bo,
    float* __restrict__ out) {
    gemm_body<0>(g_ctx, Wo, bo, out);
}

// ---------------------------------------------------------------------------
// Flash attention: one block per (q-tile of 64, batch-head).
// 256 threads, 4x4 register tile over a 64x64 score tile.
// Shared: qs[d][r] (scaled Q^T), ks[d][c] (K^T), vs[k][d]. P^T reuses ks.
// ---------------------------------------------------------------------------
__global__ void __launch_bounds__(256) attn_kernel() {
    __shared__ float qs[64 * 64];   // qs[d*64 + r]
    __shared__ float ks[64 * 64];   // ks[d*64 + c]; later pT[c*64 + r]
    __shared__ float vs[64 * 64];   // vs[k*64 + d]

    const int tid = threadIdx.x;
    const int tr = tid >> 4;    // 0..15 -> rows tr*4..tr*4+3
    const int tc = tid & 15;    // 0..15 -> cols tc*4..tc*4+3
    const int qt = blockIdx.x;  // q tile
    const int bh = blockIdx.y;  // b*H + h

    const float* Qb = g_Q + ((size_t)bh * SS + qt * 64) * DKK;
    const float* Kb = g_K + (size_t)bh * SS * DKK;
    const float* Vb = g_V + (size_t)bh * SS * DKK;

    const float scale = 0.125f;  // 1/sqrt(64)

    // Load Q tile transposed + pre-scaled
    for (int i = tid; i < 1024; i += 256) {
        int r  = i >> 4;
        int c4 = (i & 15) << 2;
        float4 v = *(const float4*)(Qb + r * 64 + c4);
        qs[(c4 + 0) * 64 + r] = v.x * scale;
        qs[(c4 + 1) * 64 + r] = v.y * scale;
        qs[(c4 + 2) * 64 + r] = v.z * scale;
        qs[(c4 + 3) * 64 + r] = v.w * scale;
    }

    float m_i[4], l_i[4], o[4][4];
#pragma unroll
    for (int i = 0; i < 4; i++) {
        m_i[i] = -1e30f;
        l_i[i] = 0.0f;
#pragma unroll
        for (int j = 0; j < 4; j++) o[i][j] = 0.0f;
    }
    __syncthreads();

    for (int kt = 0; kt < SS / 64; kt++) {
        // Load K (transposed) and V tiles
        for (int i = tid; i < 1024; i += 256) {
            int r  = i >> 4;
            int c4 = (i & 15) << 2;
            const float* kp = Kb + ((size_t)(kt * 64 + r)) * 64 + c4;
            float4 kv = *(const float4*)kp;
            ks[(c4 + 0) * 64 + r] = kv.x;
            ks[(c4 + 1) * 64 + r] = kv.y;
            ks[(c4 + 2) * 64 + r] = kv.z;
            ks[(c4 + 3) * 64 + r] = kv.w;
            const float* vp = Vb + ((size_t)(kt * 64 + r)) * 64 + c4;
            *(float4*)(vs + r * 64 + c4) = *(const float4*)vp;
        }
        __syncthreads();

        // S = (Q*scale) K^T  (64x64, each thread 4x4)
        float sacc[4][4];
#pragma unroll
        for (int i = 0; i < 4; i++)
#pragma unroll
            for (int j = 0; j < 4; j++) sacc[i][j] = 0.0f;

#pragma unroll 8
        for (int kk = 0; kk < 64; kk++) {
            float4 q = *(const float4*)(qs + kk * 64 + tr * 4);
            float4 k = *(const float4*)(ks + kk * 64 + tc * 4);
            float qa[4] = {q.x, q.y, q.z, q.w};
            float ka[4] = {k.x, k.y, k.z, k.w};
#pragma unroll
            for (int i = 0; i < 4; i++)
#pragma unroll
                for (int j = 0; j < 4; j++) sacc[i][j] += qa[i] * ka[j];
        }
        __syncthreads();   // everyone done reading ks before it becomes pT

        // Online softmax + write P^T into ks buffer
        float* pT = ks;
#pragma unroll
        for (int i = 0; i < 4; i++) {
            float mt = fmaxf(fmaxf(sacc[i][0], sacc[i][1]),
                             fmaxf(sacc[i][2], sacc[i][3]));
#pragma unroll
            for (int off = 8; off >= 1; off >>= 1)
                mt = fmaxf(mt, __shfl_xor_sync(0xffffffffu, mt, off));
            float mn = fmaxf(m_i[i], mt);
            float corr = __expf(m_i[i] - mn);
            m_i[i] = mn;
            float p[4], rs = 0.0f;
#pragma unroll
            for (int j = 0; j < 4; j++) {
                p[j] = __expf(sacc[i][j] - mn);
                rs += p[j];
            }
#pragma unroll
            for (int off = 8; off >= 1; off >>= 1)
                rs += __shfl_xor_sync(0xffffffffu, rs, off);
            l_i[i] = l_i[i] * corr + rs;
#pragma unroll
            for (int j = 0; j < 4; j++) {
                o[i][j] *= corr;
                pT[(tc * 4 + j) * 64 + tr * 4 + i] = p[j];
            }
        }
        __syncthreads();

        // O += P V   (each thread 4 rows x 4 d-cols)
#pragma unroll 8
        for (int kk = 0; kk < 64; kk++) {
            float4 p = *(const float4*)(pT + kk * 64 + tr * 4);
            float4 v = *(const float4*)(vs + kk * 64 + tc * 4);
            float pa[4] = {p.x, p.y, p.z, p.w};
            float va[4] = {v.x, v.y, v.z, v.w};
#pragma unroll
            for (int i = 0; i < 4; i++)
#pragma unroll
                for (int j = 0; j < 4; j++) o[i][j] += pa[i] * va[j];
        }
        __syncthreads();   // before next tile overwrites ks/vs
    }

    // Epilogue: ctx[b][s][h*64+d] = O / l
    const int b_ = bh >> 4;
    const int h_ = bh & 15;
#pragma unroll
    for (int i = 0; i < 4; i++) {
        int s_ = qt * 64 + tr * 4 + i;
        float inv = 1.0f / l_i[i];
#pragma unroll
        for (int j = 0; j < 4; j++) {
            int d_ = tc * 4 + j;
            g_ctx[((size_t)(b_ * SS + s_)) * DD + h_ * DKK + d_] = o[i][j] * inv;
        }
    }
}

extern "C" void kernel_launch(void* const* d_in, const int* in_sizes, int n_in,
                              void* d_out, int out_size) {
    const float* query = (const float*)d_in[0];
    const float* key_i = (const float*)d_in[1];
    const float* value = (const float*)d_in[2];
    const float* Wq = (const float*)d_in[3];
    const float* bq = (const float*)d_in[4];
    const float* Wk = (const float*)d_in[5];
    const float* bk = (const float*)d_in[6];
    const float* Wv = (const float*)d_in[7];
    const float* bv = (const float*)d_in[8];
    const float* Wo = (const float*)d_in[9];
    const float* bo = (const float*)d_in[10];
    float* out = (float*)d_out;

    dim3 gProj(DD / 128, MTOT / 128, 3);   // (8, 64, 3)
    qkv_proj_kernel<<<gProj, 256>>>(query, key_i, value, Wq, bq, Wk, bk, Wv, bv);

    dim3 gAttn(SS / 64, BB * HH);          // (32, 64)
    attn_kernel<<<gAttn, 256>>>();

    dim3 gOut(DD / 128, MTOT / 128);       // (8, 64)
    out_proj_kernel<<<gOut, 256>>>(Wo, bo, out);
}